// round 10
// baseline (speedup 1.0000x reference)
#include <cuda_runtime.h>
#include <cuda_bf16.h>

typedef unsigned long long ull;
#define FULL 0xffffffffu
#define NMAX 20000

// ---------------- scratch (static device globals; allocation-free) ----------
__device__ __align__(128) float g_s    [NMAX * 64];    // lin1 scalar out  [n][u]
__device__ __align__(128) float g_v    [NMAX * 192];   // lin1 vector out  [n][i][u]  (component-major)
__device__ __align__(128) float g_sc_s [NMAX * 128];   // self-conn scalar [n][w]
__device__ __align__(128) float g_sc_v [NMAX * 192];   // self-conn vector [n][i][w]  (component-major)
// permuted agg layouts: pos p = 4*l + 2*g + c  <->  logical u = 2*l + c of group g
__device__ __align__(128) float g_s_agg[NMAX * 128];   // [n][p]      g: 0=A(u<64) 1=D
__device__ __align__(128) float g_v_agg[NMAX * 384];   // [n][i][p]   g: 0=B       1=C

// ---------------- helpers ----------------
__device__ __forceinline__ float silu_n(float x) {
    return 1.679177f * x * __fdividef(1.0f, 1.0f + __expf(-x));
}
__device__ __forceinline__ ull pack2(float x, float y) {
    ull r; asm("mov.b64 %0, {%1, %2};" : "=l"(r) : "f"(x), "f"(y)); return r;
}
__device__ __forceinline__ float2 unp2(ull a) {
    float2 r; asm("mov.b64 {%0, %1}, %2;" : "=f"(r.x), "=f"(r.y) : "l"(a)); return r;
}
__device__ __forceinline__ void ffma2(ull& d, ull a, ull b) {
    asm("fma.rn.f32x2 %0, %1, %2, %3;" : "=l"(d) : "l"(a), "l"(b), "l"(d));
}
// no "memory" clobber — targets disjoint from all loads, REDs commute
__device__ __forceinline__ void redv4(float* p, float a, float b, float c, float d) {
    asm volatile("red.global.add.v4.f32 [%0], {%1, %2, %3, %4};"
                 :: "l"(p), "f"(a), "f"(b), "f"(c), "f"(d));
}

#define SVN 196   // padded node stride for sV (float4-aligned, bank-offset 4)

// ======================= K1: node pre (zero + lin1 + self-connection) =======
// 256 threads, 32 nodes/block.
__global__ __launch_bounds__(256, 2) void k_node_pre(
    const float* __restrict__ ns, const float* __restrict__ nv,
    const float* __restrict__ na,
    const float* __restrict__ W1s, const float* __restrict__ W1v,
    const float* __restrict__ Wscs, const float* __restrict__ Wscv)
{
    __shared__ float sS[2048];        // [n][64]
    __shared__ float sV[32 * SVN];    // [n][i*64 + u], node stride SVN
    __shared__ float sAttr[128];

    const int t  = threadIdx.x;
    const int n0 = blockIdx.x * 32;

    // ---- zero this block's aggregation slices ----
    {
        float4 z = make_float4(0.f, 0.f, 0.f, 0.f);
        float4* zs = reinterpret_cast<float4*>(&g_s_agg[(size_t)n0 * 128]);
        #pragma unroll
        for (int i = 0; i < 4; i++) zs[t + 256 * i] = z;
        float4* zv = reinterpret_cast<float4*>(&g_v_agg[(size_t)n0 * 384]);
        #pragma unroll
        for (int i = 0; i < 12; i++) zv[t + 256 * i] = z;
    }

    for (int i = t; i < 2048; i += 256) sS[i] = ns[(size_t)n0 * 64 + i];
    for (int i = t; i < 6144; i += 256) {
        int n = i / 192, r = i - n * 192, u = r / 3, c = r - u * 3;
        sV[n * SVN + c * 64 + u] = nv[(size_t)n0 * 192 + i];
    }
    if (t < 128) sAttr[t] = na[(size_t)n0 * 4 + t];
    __syncthreads();

    const int w = t & 63, g = t >> 6;   // 4 groups x 8 nodes (lin1 mapping)

    // ---- lin1 scalar: s = ns @ W1s * (1/8) ----
    {
        float acc[8];
        #pragma unroll
        for (int n = 0; n < 8; n++) acc[n] = 0.f;
        for (int k4 = 0; k4 < 64; k4 += 4) {
            float a0 = W1s[(k4 + 0) * 64 + w], a1 = W1s[(k4 + 1) * 64 + w];
            float a2 = W1s[(k4 + 2) * 64 + w], a3 = W1s[(k4 + 3) * 64 + w];
            #pragma unroll
            for (int n = 0; n < 8; n++) {
                float4 s4 = *reinterpret_cast<const float4*>(&sS[(g * 8 + n) * 64 + k4]);
                acc[n] += s4.x * a0 + s4.y * a1 + s4.z * a2 + s4.w * a3;
            }
        }
        #pragma unroll
        for (int n = 0; n < 8; n++)
            g_s[(size_t)(n0 + g * 8 + n) * 64 + w] = acc[n] * 0.125f;
    }
    // ---- lin1 vector (component-major out) ----
    {
        float acc[8][3];
        #pragma unroll
        for (int n = 0; n < 8; n++) { acc[n][0] = acc[n][1] = acc[n][2] = 0.f; }
        for (int k4 = 0; k4 < 64; k4 += 4) {
            float a0 = W1v[(k4 + 0) * 64 + w], a1 = W1v[(k4 + 1) * 64 + w];
            float a2 = W1v[(k4 + 2) * 64 + w], a3 = W1v[(k4 + 3) * 64 + w];
            #pragma unroll
            for (int n = 0; n < 8; n++)
                #pragma unroll
                for (int i = 0; i < 3; i++) {
                    float4 s4 = *reinterpret_cast<const float4*>(&sV[(g * 8 + n) * SVN + i * 64 + k4]);
                    acc[n][i] += s4.x * a0 + s4.y * a1 + s4.z * a2 + s4.w * a3;
                }
        }
        #pragma unroll
        for (int n = 0; n < 8; n++)
            #pragma unroll
            for (int i = 0; i < 3; i++)
                g_v[(size_t)(n0 + g * 8 + n) * 192 + i * 64 + w] = acc[n][i] * 0.125f;
    }

    // ---- sc_s: warp owns 4 nodes (warp-uniform) x all 128 cols ----
    // cq = t&31 -> cols 4cq..4cq+3 ; ng = t>>5 (warp) -> nodes 4ng..4ng+3
    {
        const int cq = t & 31, ng = t >> 5;
        float at[4][4];
        #pragma unroll
        for (int j = 0; j < 4; j++)
            #pragma unroll
            for (int v = 0; v < 4; v++) at[j][v] = sAttr[(4 * ng + j) * 4 + v];
        ull acc[4][2];
        #pragma unroll
        for (int j = 0; j < 4; j++) { acc[j][0] = 0ull; acc[j][1] = 0ull; }
        for (int u = 0; u < 64; u++) {
            float sv[4];
            #pragma unroll
            for (int j = 0; j < 4; j++) sv[j] = sS[(4 * ng + j) * 64 + u];  // broadcast
            #pragma unroll
            for (int v = 0; v < 4; v++) {
                ulonglong2 wq = *reinterpret_cast<const ulonglong2*>(
                    &Wscs[(size_t)(4 * u + v) * 128 + 4 * cq]);
                #pragma unroll
                for (int j = 0; j < 4; j++) {
                    float tv = sv[j] * at[j][v];
                    ull p = pack2(tv, tv);
                    ffma2(acc[j][0], p, wq.x); ffma2(acc[j][1], p, wq.y);
                }
            }
        }
        #pragma unroll
        for (int j = 0; j < 4; j++) {
            float2 p0 = unp2(acc[j][0]), p1 = unp2(acc[j][1]);
            *reinterpret_cast<float4*>(&g_sc_s[(size_t)(n0 + 4 * ng + j) * 128 + 4 * cq]) =
                make_float4(p0.x * 0.0625f, p0.y * 0.0625f, p1.x * 0.0625f, p1.y * 0.0625f);
        }
    }

    // ---- sc_v: lane-halves own 2 nodes x all 64 cols x 3 comps ----
    // cq = t&15 -> cols 4cq..4cq+3 ; ng = t>>4 -> nodes 2ng, 2ng+1
    {
        const int cq = t & 15, ng = t >> 4;
        float atv[2][4];
        #pragma unroll
        for (int n = 0; n < 2; n++)
            #pragma unroll
            for (int v = 0; v < 4; v++) atv[n][v] = sAttr[(2 * ng + n) * 4 + v];
        ull acc[2][3][2];
        #pragma unroll
        for (int n = 0; n < 2; n++)
            #pragma unroll
            for (int i = 0; i < 3; i++) { acc[n][i][0] = 0ull; acc[n][i][1] = 0ull; }
        for (int u = 0; u < 64; u++) {
            float sx[2], sy[2], sz[2];
            #pragma unroll
            for (int n = 0; n < 2; n++) {
                sx[n] = sV[(2 * ng + n) * SVN + u];
                sy[n] = sV[(2 * ng + n) * SVN + 64 + u];
                sz[n] = sV[(2 * ng + n) * SVN + 128 + u];
            }
            #pragma unroll
            for (int v = 0; v < 4; v++) {
                ulonglong2 wq = *reinterpret_cast<const ulonglong2*>(
                    &Wscv[(size_t)(4 * u + v) * 64 + 4 * cq]);
                #pragma unroll
                for (int n = 0; n < 2; n++) {
                    float a = atv[n][v];
                    float tx = sx[n] * a, ty = sy[n] * a, tz = sz[n] * a;
                    ull px = pack2(tx, tx), py = pack2(ty, ty), pz = pack2(tz, tz);
                    ffma2(acc[n][0][0], px, wq.x); ffma2(acc[n][0][1], px, wq.y);
                    ffma2(acc[n][1][0], py, wq.x); ffma2(acc[n][1][1], py, wq.y);
                    ffma2(acc[n][2][0], pz, wq.x); ffma2(acc[n][2][1], pz, wq.y);
                }
            }
        }
        #pragma unroll
        for (int n = 0; n < 2; n++)
            #pragma unroll
            for (int i = 0; i < 3; i++) {
                float2 p0 = unp2(acc[n][i][0]), p1 = unp2(acc[n][i][1]);
                *reinterpret_cast<float4*>(&g_sc_v[(size_t)(n0 + 2 * ng + n) * 192 + i * 64 + 4 * cq]) =
                    make_float4(p0.x * 0.0625f, p0.y * 0.0625f, p1.x * 0.0625f, p1.y * 0.0625f);
            }
    }
}

// ======================= K2: edge kernel (MLP + TP + scatter) ===============
// 256 threads (8 warps); 8 edges/warp/iter.  dyn smem 100352 B.
// Stage-3 weights split into two float4-stride banks (conflict-free LDS.128).
__global__ __launch_bounds__(256, 2) void k_edge(
    const float* __restrict__ emb, const float* __restrict__ esh,
    const int* __restrict__ esrc, const int* __restrict__ edst,
    const float* __restrict__ W0, const float* __restrict__ W1,
    const float* __restrict__ W2, int E)
{
    extern __shared__ float sm2[];
    float* sW2a = sm2;            // 8192  (lane cols 0-3: groups A,B)
    float* sW2b = sm2 + 8192;     // 8192  (lane cols 4-7: groups C,D)
    float* sW1  = sm2 + 16384;    // 4096  (pre-scaled 1/8)
    float* sW0_ = sm2 + 20480;    // 512   (pre-scaled 1/sqrt8)
    float* sH   = sm2 + 20992;    // 8 warps * 8 edges * 64

    const int tid = threadIdx.x;
    const float RS8 = 0.35355339059327373f;   // 1/sqrt(8)
    const float I3  = 0.5773502691896258f;    // 1/sqrt(3)
    const float SC  = 0.0078125f;             // 1/8 * 1/16
    // W2: permute + scale + split:  logical col g*64+2l+r  ->  p8 = 2g+r of lane l
    for (int idx = tid; idx < 16384; idx += 256) {
        int k = idx >> 8, c = idx & 255;
        int gg = c >> 6, u = c & 63, l = u >> 1, r = u & 1;
        int p8 = 2 * gg + r;
        float s = (gg == 3) ? SC * I3 : SC;
        float val = W2[idx] * s;
        if (p8 < 4) sW2a[k * 128 + 4 * l + p8]     = val;
        else        sW2b[k * 128 + 4 * l + p8 - 4] = val;
    }
    for (int i = tid; i < 1024; i += 256) {
        float4 v = reinterpret_cast<const float4*>(W1)[i];
        v.x *= 0.125f; v.y *= 0.125f; v.z *= 0.125f; v.w *= 0.125f;
        reinterpret_cast<float4*>(sW1)[i] = v;
    }
    for (int i = tid; i < 128; i += 256) {
        float4 v = reinterpret_cast<const float4*>(W0)[i];
        v.x *= RS8; v.y *= RS8; v.z *= RS8; v.w *= RS8;
        reinterpret_cast<float4*>(sW0_)[i] = v;
    }
    __syncthreads();

    const int warp = tid >> 5, lane = tid & 31;
    float* sHw = sH + warp * 512;

    const int noct = (E + 7) >> 3;
    for (int q = blockIdx.x * 8 + warp; q < noct; q += gridDim.x * 8) {
        const int e0 = q * 8;

        ull embp = 0ull;
        {
            int e = e0 + (lane >> 2);
            if (e < E) {
                float2 v = *reinterpret_cast<const float2*>(&emb[(size_t)e0 * 8 + 2 * lane]);
                embp = pack2(v.x, v.y);
            }
        }
        int src8[8], dst8[8];
        #pragma unroll
        for (int e = 0; e < 8; e++) {
            int ee = e0 + e;
            int ec = (ee < E) ? ee : 0;
            src8[e] = __ldg(&esrc[ec]);
            dst8[e] = __ldg(&edst[ec]);
        }

        // ---- stage1 ----
        {
            ull a1[8];
            #pragma unroll
            for (int e = 0; e < 8; e++) a1[e] = 0ull;
            #pragma unroll
            for (int kp = 0; kp < 4; kp++) {
                ull w0 = *reinterpret_cast<const ull*>(&sW0_[(2 * kp) * 64 + 2 * lane]);
                ull w1 = *reinterpret_cast<const ull*>(&sW0_[(2 * kp + 1) * 64 + 2 * lane]);
                #pragma unroll
                for (int e = 0; e < 8; e++) {
                    float2 ab = unp2(__shfl_sync(FULL, embp, e * 4 + kp));
                    ffma2(a1[e], pack2(ab.x, ab.x), w0);
                    ffma2(a1[e], pack2(ab.y, ab.y), w1);
                }
            }
            #pragma unroll
            for (int e = 0; e < 8; e++) {
                float2 p = unp2(a1[e]);
                *reinterpret_cast<float2*>(&sHw[e * 64 + 2 * lane]) =
                    make_float2(silu_n(p.x), silu_n(p.y));
            }
        }
        __syncwarp();

        // ---- stage2 ----
        {
            ull a2[8];
            #pragma unroll
            for (int e = 0; e < 8; e++) a2[e] = 0ull;
            #pragma unroll 4
            for (int k4 = 0; k4 < 64; k4 += 4) {
                ull wp0 = *reinterpret_cast<const ull*>(&sW1[(k4 + 0) * 64 + 2 * lane]);
                ull wp1 = *reinterpret_cast<const ull*>(&sW1[(k4 + 1) * 64 + 2 * lane]);
                ull wp2 = *reinterpret_cast<const ull*>(&sW1[(k4 + 2) * 64 + 2 * lane]);
                ull wp3 = *reinterpret_cast<const ull*>(&sW1[(k4 + 3) * 64 + 2 * lane]);
                #pragma unroll
                for (int e = 0; e < 8; e++) {
                    float4 hc = *reinterpret_cast<const float4*>(&sHw[e * 64 + k4]);
                    ffma2(a2[e], pack2(hc.x, hc.x), wp0);
                    ffma2(a2[e], pack2(hc.y, hc.y), wp1);
                    ffma2(a2[e], pack2(hc.z, hc.z), wp2);
                    ffma2(a2[e], pack2(hc.w, hc.w), wp3);
                }
            }
            __syncwarp();
            #pragma unroll
            for (int e = 0; e < 8; e++) {
                float2 p = unp2(a2[e]);
                *reinterpret_cast<float2*>(&sHw[e * 64 + 2 * lane]) =
                    make_float2(silu_n(p.x), silu_n(p.y));
            }
        }
        __syncwarp();

        // ---- stage3 (conflict-free weight banks) ----
        ull a3[8][4];
        #pragma unroll
        for (int e = 0; e < 8; e++)
            #pragma unroll
            for (int j = 0; j < 4; j++) a3[e][j] = 0ull;

        for (int k4 = 0; k4 < 64; k4 += 4) {
            float4 hc[8];
            #pragma unroll
            for (int e = 0; e < 8; e++)
                hc[e] = *reinterpret_cast<const float4*>(&sHw[e * 64 + k4]);
            #pragma unroll
            for (int kk = 0; kk < 4; kk++) {
                ulonglong2 wa = *reinterpret_cast<const ulonglong2*>(&sW2a[(k4 + kk) * 128 + 4 * lane]);
                ulonglong2 wb = *reinterpret_cast<const ulonglong2*>(&sW2b[(k4 + kk) * 128 + 4 * lane]);
                #pragma unroll
                for (int e = 0; e < 8; e++) {
                    float h = (kk == 0) ? hc[e].x : (kk == 1) ? hc[e].y : (kk == 2) ? hc[e].z : hc[e].w;
                    ull hp = pack2(h, h);
                    ffma2(a3[e][0], hp, wa.x);
                    ffma2(a3[e][1], hp, wa.y);
                    ffma2(a3[e][2], hp, wb.x);
                    ffma2(a3[e][3], hp, wb.y);
                }
            }
        }

        // ---- uniform tensor product + scatter ----
        #pragma unroll
        for (int e = 0; e < 8; e++) {
            int ee = e0 + e;
            float4 y;
            if (ee < E) y = __ldg(reinterpret_cast<const float4*>(&esh[(size_t)ee * 4]));
            else        y = make_float4(0.f, 0.f, 0.f, 0.f);
            const int src = src8[e], dst = dst8[e];
            float2 s2 = __ldg(reinterpret_cast<const float2*>(&g_s[(size_t)src * 64 + 2 * lane]));
            float2 vx = __ldg(reinterpret_cast<const float2*>(&g_v[(size_t)src * 192 + 0   + 2 * lane]));
            float2 vy = __ldg(reinterpret_cast<const float2*>(&g_v[(size_t)src * 192 + 64  + 2 * lane]));
            float2 vz = __ldg(reinterpret_cast<const float2*>(&g_v[(size_t)src * 192 + 128 + 2 * lane]));
            float2 wA = unp2(a3[e][0]), wB = unp2(a3[e][1]);
            float2 wC = unp2(a3[e][2]), wD = unp2(a3[e][3]);
            float d0 = vx.x * y.y + vy.x * y.z + vz.x * y.w;
            float d1 = vx.y * y.y + vy.y * y.z + vz.y * y.w;
            redv4(&g_s_agg[(size_t)dst * 128 + 4 * lane],
                  wA.x * s2.x * y.x, wA.y * s2.y * y.x, wD.x * d0, wD.y * d1);
            float b0 = wB.x * s2.x, b1 = wB.y * s2.y;
            float c0 = wC.x * y.x,  c1 = wC.y * y.x;
            float* pv = &g_v_agg[(size_t)dst * 384 + 4 * lane];
            redv4(pv,       b0 * y.y, b1 * y.y, c0 * vx.x, c1 * vx.y);
            redv4(pv + 128, b0 * y.z, b1 * y.z, c0 * vy.x, c1 * vy.y);
            redv4(pv + 256, b0 * y.w, b1 * y.w, c0 * vz.x, c1 * vz.y);
        }
    }
}

// ======================= K3: node post (lin2 + sc + gating) =================
// 256 threads, 32 nodes/block.  dyn smem = 81920 B.
__global__ __launch_bounds__(256, 2) void k_node_post(
    const float* __restrict__ W2s, const float* __restrict__ W2v,
    float* __restrict__ out)
{
    extern __shared__ float sm3[];
    float* sSA = sm3;              // [n][k]     32*128
    float* sVA = sm3 + 4096;       // [n][i][k]  32*3*128
    float* sSH = sm3 + 16384;      // 32*128

    const int t  = threadIdx.x;
    const int n0 = blockIdx.x * 32;

    // un-permute agg layouts: p = 4l+2g+c -> k = g*64 + 2l + c
    for (int i = t; i < 4096; i += 256) {
        int n = i >> 7, p = i & 127;
        int l = p >> 2, qq = p & 3, gg = qq >> 1, c = qq & 1;
        sSA[n * 128 + gg * 64 + 2 * l + c] = g_s_agg[(size_t)n0 * 128 + i];
    }
    for (int i = t; i < 12288; i += 256) {
        int n = i / 384, r = i - n * 384, comp = r >> 7, p = r & 127;
        int l = p >> 2, qq = p & 3, gg = qq >> 1, c = qq & 1;
        sVA[n * 384 + comp * 128 + gg * 64 + 2 * l + c] = g_v_agg[(size_t)n0 * 384 + i];
    }
    __syncthreads();

    const float RS128 = 0.08838834764831845f;  // 1/sqrt(128)

    // ---- s_h: warp owns 4 nodes (warp-uniform) x all 128 cols ----
    {
        const int cq = t & 31, ng = t >> 5;   // cols 4cq.. ; nodes 4ng..4ng+3
        ull acc[4][2];
        #pragma unroll
        for (int j = 0; j < 4; j++) { acc[j][0] = 0ull; acc[j][1] = 0ull; }
        for (int k = 0; k < 128; k++) {
            ulonglong2 wq = *reinterpret_cast<const ulonglong2*>(&W2s[(size_t)k * 128 + 4 * cq]);
            #pragma unroll
            for (int j = 0; j < 4; j++) {
                float s = sSA[(4 * ng + j) * 128 + k];   // broadcast
                ull p = pack2(s, s);
                ffma2(acc[j][0], p, wq.x); ffma2(acc[j][1], p, wq.y);
            }
        }
        #pragma unroll
        for (int j = 0; j < 4; j++) {
            int node = 4 * ng + j, gn = n0 + node;
            float2 p0 = unp2(acc[j][0]), p1 = unp2(acc[j][1]);
            float4 sc = *reinterpret_cast<const float4*>(&g_sc_s[(size_t)gn * 128 + 4 * cq]);
            float4 sh = make_float4(p0.x * RS128 + sc.x, p0.y * RS128 + sc.y,
                                    p1.x * RS128 + sc.z, p1.y * RS128 + sc.w);
            *reinterpret_cast<float4*>(&sSH[node * 128 + 4 * cq]) = sh;
            if (cq < 16)
                *reinterpret_cast<float4*>(&out[(size_t)gn * 256 + 4 * cq]) =
                    make_float4(silu_n(sh.x), silu_n(sh.y), silu_n(sh.z), silu_n(sh.w));
        }
    }
    __syncthreads();

    // ---- v_h + gated output: lane-halves own 2 nodes x all 64 cols x 3 comps ----
    {
        const int cq = t & 15, ng = t >> 4;   // cols 4cq.. ; nodes 2ng, 2ng+1
        ull acc[2][3][2];
        #pragma unroll
        for (int n = 0; n < 2; n++)
            #pragma unroll
            for (int i = 0; i < 3; i++) { acc[n][i][0] = 0ull; acc[n][i][1] = 0ull; }
        for (int k = 0; k < 128; k++) {
            ulonglong2 wq = *reinterpret_cast<const ulonglong2*>(&W2v[(size_t)k * 64 + 4 * cq]);
            #pragma unroll
            for (int n = 0; n < 2; n++) {
                int node = 2 * ng + n;
                float sx = sVA[node * 384 + k];
                float sy = sVA[node * 384 + 128 + k];
                float sz = sVA[node * 384 + 256 + k];
                ull px = pack2(sx, sx), py = pack2(sy, sy), pz = pack2(sz, sz);
                ffma2(acc[n][0][0], px, wq.x); ffma2(acc[n][0][1], px, wq.y);
                ffma2(acc[n][1][0], py, wq.x); ffma2(acc[n][1][1], py, wq.y);
                ffma2(acc[n][2][0], pz, wq.x); ffma2(acc[n][2][1], pz, wq.y);
            }
        }
        #pragma unroll
        for (int n = 0; n < 2; n++) {
            int node = 2 * ng + n, gn = n0 + node;
            float vh[4][3];
            #pragma unroll
            for (int i = 0; i < 3; i++) {
                float2 p0 = unp2(acc[n][i][0]), p1 = unp2(acc[n][i][1]);
                float4 sc = *reinterpret_cast<const float4*>(&g_sc_v[(size_t)gn * 192 + i * 64 + 4 * cq]);
                vh[0][i] = p0.x * RS128 + sc.x;
                vh[1][i] = p0.y * RS128 + sc.y;
                vh[2][i] = p1.x * RS128 + sc.z;
                vh[3][i] = p1.y * RS128 + sc.w;
            }
            float4 gv = *reinterpret_cast<const float4*>(&sSH[node * 128 + 64 + 4 * cq]);
            float g0 = silu_n(gv.x), g1 = silu_n(gv.y), g2 = silu_n(gv.z), g3 = silu_n(gv.w);
            float* po = &out[(size_t)gn * 256 + 64 + 12 * cq];
            *reinterpret_cast<float4*>(po) =
                make_float4(g0 * vh[0][0], g0 * vh[0][1], g0 * vh[0][2], g1 * vh[1][0]);
            *reinterpret_cast<float4*>(po + 4) =
                make_float4(g1 * vh[1][1], g1 * vh[1][2], g2 * vh[2][0], g2 * vh[2][1]);
            *reinterpret_cast<float4*>(po + 8) =
                make_float4(g2 * vh[2][2], g3 * vh[3][0], g3 * vh[3][1], g3 * vh[3][2]);
        }
    }
}

// ======================= launcher ==========================================
extern "C" void kernel_launch(void* const* d_in, const int* in_sizes, int n_in,
                              void* d_out, int out_size) {
    const int N = in_sizes[0] / 64;
    const int E = in_sizes[3] / 4;

    const float *ns, *nv, *na, *esh, *emb;
    const float *W1s, *W1v, *W0, *W1, *W2, *W2s, *W2v, *Wscs, *Wscv;
    const int *esrc, *edst;

    ns  = (const float*)d_in[0];
    nv  = (const float*)d_in[1];
    na  = (const float*)d_in[2];
    esh = (const float*)d_in[3];
    emb = (const float*)d_in[4];
    if (in_sizes[5] == E && in_sizes[6] == E) {
        esrc = (const int*)d_in[5];  edst = (const int*)d_in[6];
        W1s  = (const float*)d_in[7];  W1v  = (const float*)d_in[8];
        W0   = (const float*)d_in[9];  W1   = (const float*)d_in[10];
        W2   = (const float*)d_in[11]; W2s  = (const float*)d_in[12];
        W2v  = (const float*)d_in[13]; Wscs = (const float*)d_in[14];
        Wscv = (const float*)d_in[15];
    } else {
        W1s  = (const float*)d_in[5];  W1v  = (const float*)d_in[6];
        W0   = (const float*)d_in[7];  W1   = (const float*)d_in[8];
        W2   = (const float*)d_in[9];  W2s  = (const float*)d_in[10];
        W2v  = (const float*)d_in[11]; Wscs = (const float*)d_in[12];
        Wscv = (const float*)d_in[13];
        esrc = (const int*)d_in[14];   edst = (const int*)d_in[15];
    }
    float* out = (float*)d_out;

    cudaFuncSetAttribute(k_edge,      cudaFuncAttributeMaxDynamicSharedMemorySize, 100352);
    cudaFuncSetAttribute(k_node_post, cudaFuncAttributeMaxDynamicSharedMemorySize, 81920);

    k_node_pre<<<(N + 31) / 32, 256>>>(ns, nv, na, W1s, W1v, Wscs, Wscv);
    k_edge<<<296, 256, 100352>>>(emb, esh, esrc, edst, W0, W1, W2, E);
    k_node_post<<<(N + 31) / 32, 256, 81920>>>(W2s, W2v, out);
}